// round 13
// baseline (speedup 1.0000x reference)
#include <cuda_runtime.h>

// ---------------------------------------------------------------------------
// NextVisitTime attention, 3 launches:
//   pre1 : W2 (inline v), ts (m-trick), K2 (inline k). 216 indep blocks.
//   preC : us[b] = upt[user[b]] @ K2 (8 users/block).
//   main : 256 thr, 64 rows/block: masked softmax -> [64x96]@[96x256] fp32
//          GEMM via FFMA2 dup-att accs. Proven 95.3us dataflow + register
//          preloading of att/weights to collapse per-rowgroup LDS latency.
// ---------------------------------------------------------------------------

#define T_SLOTS 24
#define D_MODEL 256
#define B_BATCH 512
#define N_ROWS  65536
#define J_DIM   96
#define HD      64

__device__ float g_ts[T_SLOTS * J_DIM];
__device__ float g_K2[D_MODEL * J_DIM];      // scale folded in
__device__ float g_us[B_BATCH * J_DIM];
__device__ float g_W2[J_DIM * D_MODEL];

typedef unsigned long long u64;

__device__ __forceinline__ u64 pack_dup(float x) {
    u64 r; asm("mov.b64 %0, {%1, %1};" : "=l"(r) : "f"(x)); return r;
}
__device__ __forceinline__ u64 pack2(float x, float y) {
    u64 r; asm("mov.b64 %0, {%1, %2};" : "=l"(r) : "f"(x), "f"(y)); return r;
}
__device__ __forceinline__ void fma2(u64 &c, u64 a, u64 b) {
    asm("fma.rn.f32x2 %0, %1, %2, %0;" : "+l"(c) : "l"(a), "l"(b));
}
__device__ __forceinline__ float2 unpack2(u64 v) {
    float2 r; asm("mov.b64 {%0, %1}, %2;" : "=f"(r.x), "=f"(r.y) : "l"(v)); return r;
}

// ===========================================================================
// PRE1: 216 independent blocks (proven).
//   [0,96):    W2 row j (inline v)
//   [96,120):  ts row th (inline tq, m-trick over Wk)
//   [120,216): K2 col j (inline k head slice)
// ===========================================================================
__global__ __launch_bounds__(256) void pre1_kernel(
    const float* __restrict__ ts_emb,
    const float* __restrict__ Wq, const float* __restrict__ bq,
    const float* __restrict__ Wk, const float* __restrict__ bk,
    const float* __restrict__ Wv, const float* __restrict__ bv,
    const float* __restrict__ Wu)
{
    int bx = blockIdx.x, tid = threadIdx.x;

    if (bx < 96) {
        int j = bx, h = j / T_SLOTS, t = j % T_SLOTS;
        __shared__ __align__(16) float semb[D_MODEL];
        __shared__ __align__(16) float sv[HD];
        semb[tid] = ts_emb[t * D_MODEL + tid];
        __syncthreads();
        float a[8];
        a[0] = bv[tid];
        #pragma unroll
        for (int i = 1; i < 8; i++) a[i] = 0.f;
        #pragma unroll 4
        for (int c = 0; c < D_MODEL; c += 8) {
            #pragma unroll
            for (int u = 0; u < 8; u++)
                a[u] = fmaf(semb[c + u], Wv[(c + u) * D_MODEL + tid], a[u]);
        }
        float vd = ((a[0]+a[1])+(a[2]+a[3])) + ((a[4]+a[5])+(a[6]+a[7]));
        if (tid >= h * HD && tid < h * HD + HD) sv[tid - h * HD] = vd;
        __syncthreads();
        float b[8];
        #pragma unroll
        for (int i = 0; i < 8; i++) b[i] = 0.f;
        #pragma unroll 2
        for (int e = 0; e < HD; e += 8) {
            #pragma unroll
            for (int u = 0; u < 8; u++)
                b[u] = fmaf(sv[e + u], Wu[(h * HD + e + u) * D_MODEL + tid], b[u]);
        }
        g_W2[j * D_MODEL + tid] =
            ((b[0]+b[1])+(b[2]+b[3])) + ((b[4]+b[5])+(b[6]+b[7]));

    } else if (bx < 120) {
        int th = bx - 96;
        __shared__ __align__(16) float semb[D_MODEL];
        __shared__ __align__(16) float stq[D_MODEL];
        __shared__ __align__(16) float smm[D_MODEL * 4];
        __shared__ float stbk[4];
        semb[tid] = ts_emb[th * D_MODEL + tid];
        __syncthreads();
        float a[8];
        a[0] = bq[tid];
        #pragma unroll
        for (int i = 1; i < 8; i++) a[i] = 0.f;
        #pragma unroll 4
        for (int c = 0; c < D_MODEL; c += 8) {
            #pragma unroll
            for (int u = 0; u < 8; u++)
                a[u] = fmaf(semb[c + u], Wq[(D_MODEL + c + u) * D_MODEL + tid], a[u]);
        }
        stq[tid] = ((a[0]+a[1])+(a[2]+a[3])) + ((a[4]+a[5])+(a[6]+a[7]));
        __syncthreads();
        {
            const float4* wr = (const float4*)(Wk + (size_t)tid * D_MODEL);
            const float4* q4 = (const float4*)stq;
            #pragma unroll
            for (int h = 0; h < 4; h++) {
                float s0 = 0.f, s1 = 0.f, s2 = 0.f, s3 = 0.f;
                #pragma unroll 4
                for (int e4 = h * 16; e4 < h * 16 + 16; e4++) {
                    float4 wv = wr[e4], qv = q4[e4];
                    s0 = fmaf(qv.x, wv.x, s0); s1 = fmaf(qv.y, wv.y, s1);
                    s2 = fmaf(qv.z, wv.z, s2); s3 = fmaf(qv.w, wv.w, s3);
                }
                smm[tid * 4 + h] = (s0 + s1) + (s2 + s3);
            }
        }
        if (tid < 4) {
            float s = 0.f;
            for (int e = 0; e < HD; e++)
                s = fmaf(stq[tid * HD + e], bk[tid * HD + e], s);
            stbk[tid] = s;
        }
        __syncthreads();
        if (tid < J_DIM) {
            int h = tid / T_SLOTS, t = tid % T_SLOTS;
            const float* er = ts_emb + t * D_MODEL;
            float s0 = 0.f, s1 = 0.f, s2 = 0.f, s3 = 0.f;
            #pragma unroll 8
            for (int c = 0; c < D_MODEL; c += 4) {
                s0 = fmaf(er[c+0], smm[(c+0)*4 + h], s0);
                s1 = fmaf(er[c+1], smm[(c+1)*4 + h], s1);
                s2 = fmaf(er[c+2], smm[(c+2)*4 + h], s2);
                s3 = fmaf(er[c+3], smm[(c+3)*4 + h], s3);
            }
            g_ts[th * J_DIM + tid] =
                (((s0 + s1) + (s2 + s3)) + stbk[h]) * 0.125f;
        }

    } else {
        int j = bx - 120;
        int h = j / T_SLOTS, t = j % T_SLOTS;
        __shared__ __align__(16) float semb[D_MODEL];
        __shared__ float part[4][HD];
        __shared__ __align__(16) float kh[HD];
        semb[tid] = ts_emb[t * D_MODEL + tid];
        __syncthreads();
        {
            int e = tid & 63, ch = tid >> 6;
            const float* wk = Wk + (size_t)(ch * 64) * D_MODEL + h * HD + e;
            float s = 0.f;
            #pragma unroll 8
            for (int cc = 0; cc < 64; cc++)
                s = fmaf(semb[ch * 64 + cc], wk[cc * D_MODEL], s);
            part[ch][e] = s;
        }
        __syncthreads();
        if (tid < HD)
            kh[tid] = ((part[0][tid] + part[1][tid]) +
                       (part[2][tid] + part[3][tid])) + bk[h * HD + tid];
        __syncthreads();
        {
            const float4* wq = (const float4*)(Wq + (size_t)tid * D_MODEL + h * HD);
            const float4* k4 = (const float4*)kh;
            float s0 = 0.f, s1 = 0.f, s2 = 0.f, s3 = 0.f;
            #pragma unroll
            for (int e4 = 0; e4 < HD / 4; e4++) {
                float4 wv = wq[e4], kv = k4[e4];
                s0 = fmaf(wv.x, kv.x, s0); s1 = fmaf(wv.y, kv.y, s1);
                s2 = fmaf(wv.z, kv.z, s2); s3 = fmaf(wv.w, kv.w, s3);
            }
            g_K2[tid * J_DIM + j] = ((s0 + s1) + (s2 + s3)) * 0.125f;
        }
    }
}

// ===========================================================================
// PREC: us[b] = upt[user[b]] @ K2  (8 users per block, 96 threads) — proven.
// ===========================================================================
__global__ __launch_bounds__(96) void preC_kernel(const int* __restrict__ user,
                                                  const float* __restrict__ upt)
{
    __shared__ float srow[8][D_MODEL];
    int b0 = blockIdx.x * 8;
    int j  = threadIdx.x;            // 0..95
    #pragma unroll
    for (int i = 0; i < 8; i++) {
        const float* src = upt + (size_t)__ldg(user + b0 + i) * D_MODEL;
        for (int d = j; d < D_MODEL; d += 96) srow[i][d] = src[d];
    }
    __syncthreads();
    float acc[8];
    #pragma unroll
    for (int i = 0; i < 8; i++) acc[i] = 0.0f;
    #pragma unroll 8
    for (int c = 0; c < D_MODEL; c++) {
        float w = g_K2[c * J_DIM + j];
        #pragma unroll
        for (int i = 0; i < 8; i++) acc[i] = fmaf(srow[i][c], w, acc[i]);
    }
    #pragma unroll
    for (int i = 0; i < 8; i++) g_us[(b0 + i) * J_DIM + j] = acc[i];
}

// ===========================================================================
// MAIN: 256 threads, 64 rows/block, 1024 blocks (the proven 95.3us shape).
// SMEM (floats): W2 24576 | attDup 64 x 98 u64 | ts 2304 | us 96
// Phase 2: warp w: colhalf cs=w>>2, rowgroup rgrp=(w&3)*2+(l>>4), 8 rows;
//   thread: 8 rows x 8 f32 (u128 cols cb, cb+16). Change vs proven version:
//   preload ALL 8 att ulonglong2 + 4 weight vectors into registers before
//   the FMA block -> one LDS latency exposure per j-pair instead of eight.
// ===========================================================================
#define SM_W2       0
#define ATT_PITCH64 98
#define SM_ATT      24576
#define SM_TS       (SM_ATT + 64 * ATT_PITCH64 * 2)  // 37120
#define SM_US       (SM_TS + T_SLOTS * J_DIM)        // 39424
#define SM_FLOATS   (SM_US + J_DIM)                  // 39520
#define SM_BYTES    (SM_FLOATS * 4)                  // 158080

__global__ __launch_bounds__(256, 1) void main_kernel(
    const int* __restrict__ hour, const int* __restrict__ hmask,
    const float* __restrict__ bu, float* __restrict__ out)
{
    extern __shared__ float sm[];
    float* sW2  = sm + SM_W2;
    u64*   sAtt = (u64*)(sm + SM_ATT);
    float* sTs  = sm + SM_TS;
    float* sUs  = sm + SM_US;

    int tid = threadIdx.x;
    int n0  = blockIdx.x * 64;
    int b   = n0 >> 7;                 // 64 | 128 -> one batch row per block

    // cooperative loads
    {
        const float4* s1 = (const float4*)g_W2;
        float4* d1 = (float4*)sW2;
        #pragma unroll
        for (int i = 0; i < 24; i++) d1[tid + i * 256] = s1[tid + i * 256];
        const float4* s2 = (const float4*)g_ts;
        float4* d2 = (float4*)sTs;
        for (int i = tid; i < (T_SLOTS * J_DIM) / 4; i += 256) d2[i] = s2[i];
        if (tid < J_DIM / 4)
            ((float4*)sUs)[tid] = ((const float4*)(g_us + b * J_DIM))[tid];
    }
    __syncthreads();

    // ---- phase 1: one (row, head) softmax per thread, dup-stored ----
    {
        int r = tid >> 2, h = tid & 3;
        int n = n0 + r;
        int hh = __ldg(hour + n);
        int msk[T_SLOTS];
        const int4* mp = (const int4*)(hmask + (size_t)n * T_SLOTS);
        #pragma unroll
        for (int i = 0; i < 6; i++) {
            int4 q = mp[i];
            msk[4*i] = q.x; msk[4*i+1] = q.y; msk[4*i+2] = q.z; msk[4*i+3] = q.w;
        }
        const float* usb = sUs + h * T_SLOTS;
        const float* tsb = sTs + hh * J_DIM + h * T_SLOTS;
        float sc[T_SLOTS];
        float mx = -3.0e38f;
        #pragma unroll
        for (int t = 0; t < T_SLOTS; t++) {
            sc[t] = msk[t] ? -1e9f : (usb[t] + tsb[t]);
            mx = fmaxf(mx, sc[t]);
        }
        float s = 0.0f;
        #pragma unroll
        for (int t = 0; t < T_SLOTS; t++) {
            float e = __expf(sc[t] - mx);
            sc[t] = e; s += e;
        }
        float inv = 1.0f / s;
        u64* ar = sAtt + r * ATT_PITCH64 + h * T_SLOTS;
        #pragma unroll
        for (int t = 0; t < T_SLOTS; t++) ar[t] = pack_dup(sc[t] * inv);
    }
    __syncthreads();

    // ---- phase 2: [64 x 96] @ [96 x 256] ----
    int w  = tid >> 5, l = tid & 31;
    int cs = w >> 2;                    // column half
    int rgrp = (w & 3) * 2 + (l >> 4);  // 0..7
    int r0 = rgrp * 8;
    int cl = l & 15;
    int cb = cs * 32 + cl;              // u128 col base (i adds 16)

    u64 acc[8][2][2];
    #pragma unroll
    for (int i = 0; i < 2; i++) {
        float4 bv = __ldg((const float4*)bu + cb + 16 * i);
        u64 blo = pack2(bv.x, bv.y), bhi = pack2(bv.z, bv.w);
        #pragma unroll
        for (int rr = 0; rr < 8; rr++) { acc[rr][i][0] = blo; acc[rr][i][1] = bhi; }
    }
    const ulonglong2* w2p = (const ulonglong2*)sW2;   // 64 u128 per j-row
    const u64* ap = sAtt + r0 * ATT_PITCH64;
    #pragma unroll 2
    for (int j = 0; j < J_DIM; j += 2) {
        // preload everything for this j-pair before any FMA
        ulonglong2 a[8];
        #pragma unroll
        for (int rr = 0; rr < 8; rr++)
            a[rr] = *(const ulonglong2*)(ap + rr * ATT_PITCH64 + j);
        ulonglong2 wa0 = w2p[j * 64 + cb];
        ulonglong2 wa1 = w2p[j * 64 + cb + 16];
        ulonglong2 wb0 = w2p[(j + 1) * 64 + cb];
        ulonglong2 wb1 = w2p[(j + 1) * 64 + cb + 16];
        #pragma unroll
        for (int rr = 0; rr < 8; rr++) {
            fma2(acc[rr][0][0], a[rr].x, wa0.x);
            fma2(acc[rr][0][1], a[rr].x, wa0.y);
            fma2(acc[rr][1][0], a[rr].x, wa1.x);
            fma2(acc[rr][1][1], a[rr].x, wa1.y);
            fma2(acc[rr][0][0], a[rr].y, wb0.x);
            fma2(acc[rr][0][1], a[rr].y, wb0.y);
            fma2(acc[rr][1][0], a[rr].y, wb1.x);
            fma2(acc[rr][1][1], a[rr].y, wb1.y);
        }
    }
    #pragma unroll
    for (int rr = 0; rr < 8; rr++) {
        float4* orow = (float4*)(out + (size_t)(n0 + r0 + rr) * D_MODEL);
        #pragma unroll
        for (int i = 0; i < 2; i++) {
            float2 lo = unpack2(acc[rr][i][0]);
            float2 hi = unpack2(acc[rr][i][1]);
            orow[cb + 16 * i] = make_float4(lo.x, lo.y, hi.x, hi.y);
        }
    }
}

extern "C" void kernel_launch(void* const* d_in, const int* in_sizes, int n_in,
                              void* d_out, int out_size) {
    const float* ts_emb = (const float*)d_in[0];
    const int*   user   = (const int*)  d_in[1];
    const int*   hour   = (const int*)  d_in[2];
    const int*   hmask  = (const int*)  d_in[3];
    const float* upt    = (const float*)d_in[4];
    const float* Wq     = (const float*)d_in[5];
    const float* bq     = (const float*)d_in[6];
    const float* Wk     = (const float*)d_in[7];
    const float* bk     = (const float*)d_in[8];
    const float* Wv     = (const float*)d_in[9];
    const float* bv     = (const float*)d_in[10];
    const float* Wu     = (const float*)d_in[11];
    const float* bu     = (const float*)d_in[12];
    float* out = (float*)d_out;

    pre1_kernel<<<216, 256>>>(ts_emb, Wq, bq, Wk, bk, Wv, bv, Wu);
    preC_kernel<<<B_BATCH / 8, 96>>>(user, upt);

    cudaFuncSetAttribute(main_kernel, cudaFuncAttributeMaxDynamicSharedMemorySize, SM_BYTES);
    main_kernel<<<N_ROWS / 64, 256, SM_BYTES>>>(hour, hmask, bu, out);
}